// round 1
// baseline (speedup 1.0000x reference)
#include <cuda_runtime.h>
#include <math.h>

#define J 23
#define BLK 256

__device__ __constant__ int c_par[J] = {-1, 0, 1, 1, 3, 4, 5, 4, 7, 4, 9, 1, 11, 12, 13, 12, 15, 12, 17, 0, 19, 0, 21};

// A matrices (rows 0..2 of each 4x4, row-major 12 floats per joint) + scalars,
// produced by k_pose, consumed by k_lbs.
__device__ float g_A[J * 12];
__device__ float g_c;       // 0.0035 * scale
__device__ float g_off[3];  // loc + 0.1*tanh(displacement)

__global__ void k_pose(const float* __restrict__ jr,
                       const float* __restrict__ j0, const float* __restrict__ j1,
                       const float* __restrict__ j2, const float* __restrict__ j3,
                       const float* __restrict__ j4, const float* __restrict__ j5,
                       const float* __restrict__ j12, const float* __restrict__ j13,
                       const float* __restrict__ disp, const float* __restrict__ scl,
                       const float* __restrict__ loc,
                       float* __restrict__ out,
                       long long poseOff, long long jointsOff,
                       long long scaleOff, long long dispOff)
{
    __shared__ float sT[J][12];   // local transforms, rows 0..2 (row 3 implicit [0,0,0,1])
    const float PI = 3.14159265358979323846f;
    int j = threadIdx.x;

    if (j < J) {
        // --- pose vector for this joint ---
        float amp = 0.f, sy = 1.f, sz = 1.f;
        const float* src = nullptr;
        switch (j) {
            case 0:  amp = PI / 2.f; src = j0;  break;
            case 1:  amp = PI / 4.f; src = j1;  break;
            case 2:  amp = PI / 9.f; src = j2;  break;
            case 3:  amp = PI / 3.f; src = j3;  break;
            case 11: amp = PI / 3.f; src = j3;  sy = -1.f; sz = -1.f; break;
            case 4:  amp = PI / 3.f; src = j4;  break;
            case 5:  amp = PI / 3.f; src = j5;  break;
            case 12: amp = PI / 3.f; src = j12; break;
            case 13: amp = PI / 3.f; src = j13; break;
        }
        float px = 0.f, py = 0.f, pz = 0.f;
        if (src) {
            px = amp * tanhf(src[0]);
            py = amp * sy * tanhf(src[1]);
            pz = amp * sz * tanhf(src[2]);
        }
        out[poseOff + j * 3 + 0] = px;
        out[poseOff + j * 3 + 1] = py;
        out[poseOff + j * 3 + 2] = pz;

        // --- Rodrigues ---
        float ang = sqrtf(px * px + py * py + pz * pz + 1e-12f);
        float inv = 1.f / ang;
        float x = px * inv, y = py * inv, z = pz * inv;
        float s = sinf(ang), c = cosf(ang), t = 1.f - c;
        float R00 = 1.f + t * (-(y * y + z * z));
        float R01 = -s * z + t * (x * y);
        float R02 =  s * y + t * (x * z);
        float R10 =  s * z + t * (x * y);
        float R11 = 1.f + t * (-(x * x + z * z));
        float R12 = -s * x + t * (y * z);
        float R20 = -s * y + t * (x * z);
        float R21 =  s * x + t * (y * z);
        float R22 = 1.f + t * (-(x * x + y * y));

        int p = c_par[j];
        float rx = jr[j * 3 + 0] - (p >= 0 ? jr[p * 3 + 0] : 0.f);
        float ry = jr[j * 3 + 1] - (p >= 0 ? jr[p * 3 + 1] : 0.f);
        float rz = jr[j * 3 + 2] - (p >= 0 ? jr[p * 3 + 2] : 0.f);

        sT[j][0] = R00; sT[j][1] = R01; sT[j][2]  = R02; sT[j][3]  = rx;
        sT[j][4] = R10; sT[j][5] = R11; sT[j][6]  = R12; sT[j][7]  = ry;
        sT[j][8] = R20; sT[j][9] = R21; sT[j][10] = R22; sT[j][11] = rz;
    }
    __syncthreads();

    if (j < J) {
        // G_j = T_root @ ... @ T_parent @ T_j : accumulate from the right walking up.
        float G[12];
        #pragma unroll
        for (int k = 0; k < 12; k++) G[k] = sT[j][k];
        int a = c_par[j];
        while (a >= 0) {
            const float* L = sT[a];
            float N[12];
            #pragma unroll
            for (int r = 0; r < 3; r++) {
                float l0 = L[r * 4 + 0], l1 = L[r * 4 + 1], l2 = L[r * 4 + 2], l3 = L[r * 4 + 3];
                N[r * 4 + 0] = l0 * G[0] + l1 * G[4] + l2 * G[8];
                N[r * 4 + 1] = l0 * G[1] + l1 * G[5] + l2 * G[9];
                N[r * 4 + 2] = l0 * G[2] + l1 * G[6] + l2 * G[10];
                N[r * 4 + 3] = l0 * G[3] + l1 * G[7] + l2 * G[11] + l3;
            }
            #pragma unroll
            for (int k = 0; k < 12; k++) G[k] = N[k];
            a = c_par[a];
        }

        float pjx = G[3], pjy = G[7], pjz = G[11];
        float jx = jr[j * 3 + 0], jy = jr[j * 3 + 1], jz = jr[j * 3 + 2];
        float tcx = G[0] * jx + G[1] * jy + G[2]  * jz;
        float tcy = G[4] * jx + G[5] * jy + G[6]  * jz;
        float tcz = G[8] * jx + G[9] * jy + G[10] * jz;

        // A = G with corrected translation
        G[3] -= tcx; G[7] -= tcy; G[11] -= tcz;
        #pragma unroll
        for (int k = 0; k < 12; k++) g_A[j * 12 + k] = G[k];

        float c0 = 0.0035f * scl[0];
        float ox = loc[0] + 0.1f * tanhf(disp[0]);
        float oy = loc[1] + 0.1f * tanhf(disp[1]);
        float oz = loc[2] + 0.1f * tanhf(disp[2]);
        out[jointsOff + j * 3 + 0] = c0 * pjx + ox;
        out[jointsOff + j * 3 + 1] = c0 * pjy + oy;
        out[jointsOff + j * 3 + 2] = c0 * pjz + oz;

        if (j == 0) {
            g_c = c0;
            g_off[0] = ox; g_off[1] = oy; g_off[2] = oz;
            out[scaleOff] = scl[0];
            out[dispOff + 0] = disp[0];
            out[dispOff + 1] = disp[1];
            out[dispOff + 2] = disp[2];
        }
    }
}

__global__ __launch_bounds__(BLK) void k_lbs(
    const float* __restrict__ vt, const float* __restrict__ skin,
    const float* __restrict__ la, float* __restrict__ out,
    int V, int B, long long laOff)
{
    __shared__ __align__(16) float sA[J * 12];
    __shared__ __align__(16) float sS[BLK * J];

    int tid = threadIdx.x;
    long long base = (long long)blockIdx.x * BLK;
    int nv = min(BLK, V - (int)base);

    if (tid < J * 12) sA[tid] = g_A[tid];

    // Coalesced float4 stage of this block's skinning rows.
    int nf = nv * J;
    {
        const float4* src4 = reinterpret_cast<const float4*>(skin + base * J);
        float4* dst4 = reinterpret_cast<float4*>(sS);
        int n4 = nf >> 2;
        for (int k = tid; k < n4; k += BLK) dst4[k] = src4[k];
        for (int k = (n4 << 2) + tid; k < nf; k += BLK) sS[k] = skin[base * J + k];
    }
    __syncthreads();

    if (tid < nv) {
        long long v = base + tid;

        // Blend T = sum_j w_j * A_j  (rows 0..2 of 4x4)
        float T[12];
        #pragma unroll
        for (int k = 0; k < 12; k++) T[k] = 0.f;
        const float* w = &sS[tid * J];
        #pragma unroll
        for (int j = 0; j < J; j++) {
            float wj = w[j];
            float4 a0 = *reinterpret_cast<const float4*>(sA + j * 12 + 0);
            float4 a1 = *reinterpret_cast<const float4*>(sA + j * 12 + 4);
            float4 a2 = *reinterpret_cast<const float4*>(sA + j * 12 + 8);
            T[0] = fmaf(wj, a0.x, T[0]); T[1] = fmaf(wj, a0.y, T[1]);
            T[2] = fmaf(wj, a0.z, T[2]); T[3] = fmaf(wj, a0.w, T[3]);
            T[4] = fmaf(wj, a1.x, T[4]); T[5] = fmaf(wj, a1.y, T[5]);
            T[6] = fmaf(wj, a1.z, T[6]); T[7] = fmaf(wj, a1.w, T[7]);
            T[8] = fmaf(wj, a2.x, T[8]); T[9] = fmaf(wj, a2.y, T[9]);
            T[10] = fmaf(wj, a2.z, T[10]); T[11] = fmaf(wj, a2.w, T[11]);
        }

        float la0 = la[v * 3 + 0], la1 = la[v * 3 + 1], la2 = la[v * 3 + 2];
        float v0 = vt[v * 3 + 0] + 0.1f * tanhf(la0);
        float v1 = vt[v * 3 + 1] + 0.1f * tanhf(la1);
        float v2 = vt[v * 3 + 2] + 0.1f * tanhf(la2);

        float p0 = T[0] * v0 + T[1] * v1 + T[2]  * v2 + T[3];
        float p1 = T[4] * v0 + T[5] * v1 + T[6]  * v2 + T[7];
        float p2 = T[8] * v0 + T[9] * v1 + T[10] * v2 + T[11];

        float cc = g_c;
        float o0 = fmaf(cc, p0, g_off[0]);
        float o1 = fmaf(cc, p1, g_off[1]);
        float o2 = fmaf(cc, p2, g_off[2]);

        long long vb = v * 3;
        long long stride = 3LL * V;
        for (int b = 0; b < B; b++) {
            long long o = (long long)b * stride + vb;
            out[o + 0] = o0; out[o + 1] = o1; out[o + 2] = o2;
        }
        // local_adjust passthrough (already in registers; avoids a second DRAM read)
        out[laOff + vb + 0] = la0;
        out[laOff + vb + 1] = la1;
        out[laOff + vb + 2] = la2;
    }
}

extern "C" void kernel_launch(void* const* d_in, const int* in_sizes, int n_in,
                              void* d_out, int out_size)
{
    const float* vt   = (const float*)d_in[0];
    const float* skin = (const float*)d_in[1];
    const float* jr   = (const float*)d_in[2];
    const float* j0   = (const float*)d_in[3];
    const float* j1   = (const float*)d_in[4];
    const float* j2   = (const float*)d_in[5];
    const float* j3   = (const float*)d_in[6];
    const float* j4   = (const float*)d_in[7];
    const float* j5   = (const float*)d_in[8];
    const float* j12  = (const float*)d_in[9];
    const float* j13  = (const float*)d_in[10];
    const float* la   = (const float*)d_in[11];
    const float* disp = (const float*)d_in[12];
    const float* scl  = (const float*)d_in[13];
    const float* loc  = (const float*)d_in[14];

    int V = in_sizes[0] / 3;
    long long tail = 2LL * (3 * J) + 1 + 3;              // pose + joints + scale + disp
    long long B = ((long long)out_size - tail - 3LL * V) / (3LL * V);

    long long poseOff   = B * 3LL * V;
    long long jointsOff = poseOff + 3 * J;
    long long scaleOff  = jointsOff + 3 * J;
    long long dispOff   = scaleOff + 1;
    long long laOff     = dispOff + 3;

    float* out = (float*)d_out;

    k_pose<<<1, 32>>>(jr, j0, j1, j2, j3, j4, j5, j12, j13,
                      disp, scl, loc, out, poseOff, jointsOff, scaleOff, dispOff);

    int blocks = (V + BLK - 1) / BLK;
    k_lbs<<<blocks, BLK>>>(vt, skin, la, out, V, (int)B, laOff);
}